// round 9
// baseline (speedup 1.0000x reference)
#include <cuda_runtime.h>
#include <cstdint>
#include <math.h>

// Problem constants (fixed by setup_inputs)
#define VOCAB   512
#define EMB     256
#define HID     64
#define N_POS   (32 * 4096)   // B * L = 131072
#define N_STEPS 5
#define DT_F32  0.01f         // float32(T_HORIZON / steps)
#define TINY_F  1.17549435082228750797e-38f  // finfo(float32).tiny
#define EPS2    1e-3f         // fast/exact gumbel margin (fast-log err ~3e-6)
#define NEG_INF __int_as_float(0xff800000)
#define POS_PER_BLOCK 512

// -------- scratch: __device__ globals only --------
__device__ float    g_T[VOCAB * VOCAB];   // intensity table
__device__ uint32_t g_thr[VOCAB * VOCAB]; // accept threshold (bits-space)
__device__ uint32_t g_pubm[VOCAB];        // max_{v!=s} thr[s][v]
__device__ int      g_state[2][N_POS];    // ping-pong state buffers
__device__ int      g_viol[3];            // detect violations (zeroed by k_emit)

// mode: 0 = A is x(int32), 1 = A is x(f32), 2 = B is x(int32), 3 = B is x(f32)
__device__ __forceinline__ int get_xmode() {
    if (!g_viol[0]) return 0;
    if (!g_viol[1]) return 1;
    if (!g_viol[2]) return 2;
    return 3;
}

// ===================== threefry-2x32 (exact JAX schedule) =====================
__device__ __forceinline__ void tf_round(uint32_t& x0, uint32_t& x1, int r) {
    x0 += x1;
    x1 = __funnelshift_l(x1, x1, r);
    x1 ^= x0;
}

__device__ __forceinline__ uint2 tf2x32(uint32_t k0, uint32_t k1,
                                        uint32_t x0, uint32_t x1) {
    uint32_t ks2 = k0 ^ k1 ^ 0x1BD11BDAu;
    x0 += k0; x1 += k1;
    tf_round(x0,x1,13); tf_round(x0,x1,15); tf_round(x0,x1,26); tf_round(x0,x1, 6);
    x0 += k1;  x1 += ks2 + 1u;
    tf_round(x0,x1,17); tf_round(x0,x1,29); tf_round(x0,x1,16); tf_round(x0,x1,24);
    x0 += ks2; x1 += k0 + 2u;
    tf_round(x0,x1,13); tf_round(x0,x1,15); tf_round(x0,x1,26); tf_round(x0,x1, 6);
    x0 += k0;  x1 += k1 + 3u;
    tf_round(x0,x1,17); tf_round(x0,x1,29); tf_round(x0,x1,16); tf_round(x0,x1,24);
    x0 += k1;  x1 += ks2 + 4u;
    tf_round(x0,x1,13); tf_round(x0,x1,15); tf_round(x0,x1,26); tf_round(x0,x1, 6);
    x0 += ks2; x1 += k0 + 5u;
    return make_uint2(x0, x1);
}

static inline uint32_t h_rotl(uint32_t x, int r) { return (x << r) | (x >> (32 - r)); }
static void h_tf2x32(uint32_t k0, uint32_t k1, uint32_t x0, uint32_t x1,
                     uint32_t& o0, uint32_t& o1) {
    uint32_t ks2 = k0 ^ k1 ^ 0x1BD11BDAu;
    static const int R[20] = {13,15,26,6, 17,29,16,24, 13,15,26,6, 17,29,16,24, 13,15,26,6};
    x0 += k0; x1 += k1;
    const uint32_t ks[3] = {k0, k1, ks2};
    for (int g = 0; g < 5; g++) {
        for (int j = 0; j < 4; j++) {
            int r = R[g * 4 + j];
            x0 += x1; x1 = h_rotl(x1, r); x1 ^= x0;
        }
        x0 += ks[(g + 1) % 3];
        x1 += ks[(g + 2) % 3] + (uint32_t)(g + 1);
    }
    o0 = x0; o1 = x1;
}

__device__ __forceinline__ uint32_t jax_bits32(uint32_t k0, uint32_t k1, uint32_t idx) {
    uint2 r = tf2x32(k0, k1, 0u, idx);
    return r.x ^ r.y;
}

__device__ __forceinline__ float bits_to_u01(uint32_t bits) {
    return __uint_as_float((bits >> 9) | 0x3f800000u) - 1.0f;
}

// ===================== io kernels =====================
// DIAGNOSTIC fallback: mapping failed -> constant 1000.0f
__global__ void k_fallback(float* __restrict__ out) {
    int i = blockIdx.x * blockDim.x + threadIdx.x;
    if (i < N_POS) out[i] = 1000.0f;
}

// Classify the ambiguous pair. Violation flags start 0 (module load) and are
// re-zeroed by k_emit at the end of every kernel_launch -> deterministic.
__global__ void k_detect(const uint32_t* __restrict__ A,
                         const uint32_t* __restrict__ B) {
    int stride = gridDim.x * blockDim.x;
    int vAI = 0, vAF = 0, vBI = 0;
    for (int i = blockIdx.x * blockDim.x + threadIdx.x; i < N_POS; i += stride) {
        uint32_t wa = A[i], wb = B[i];
        if (wa >= 512u) vAI = 1;
        if (!(wa == 0u || (wa >= 0x3f800000u && wa <= 0x43ff8000u))) vAF = 1;
        if (wb >= 512u) vBI = 1;
    }
    if (vAI) atomicOr(&g_viol[0], 1);
    if (vAF) atomicOr(&g_viol[1], 1);
    if (vBI) atomicOr(&g_viol[2], 1);
}

// emit final state; also re-zero detect flags for the next (replayed) call
__global__ void k_emit(float* __restrict__ out) {
    int i = blockIdx.x * blockDim.x + threadIdx.x;
    if (i >= N_POS) return;
    out[i] = (float)g_state[N_STEPS & 1][i];
    if (i < 3) g_viol[i] = 0;
}

// ===================== fused table kernel (one block per state s) =============
// emb row -> smem; H chains (sequential k, single accumulator: bit-identical);
// then T/thr for all 512 v; in-block max reduce -> pubm[s].
__global__ void __launch_bounds__(256)
k_table_fused(const void* __restrict__ A, const void* __restrict__ B,
              const float* __restrict__ W1, const float* __restrict__ b1,
              const float* __restrict__ W2, const float* __restrict__ b2) {
    __shared__ float sE[EMB];
    __shared__ float sH[HID];
    __shared__ uint32_t sMax[8];
    int s = blockIdx.x;
    int tid = threadIdx.x;
    const float* emb = (const float*)((get_xmode() < 2) ? B : A);  // non-x buffer

    if (tid < EMB / 4)
        ((float4*)sE)[tid] = ((const float4*)(emb + s * EMB))[tid];
    __syncthreads();

    if (tid < HID) {
        float acc = 0.0f;
        #pragma unroll 8
        for (int k = 0; k < EMB; k++)
            acc = fmaf(sE[k], W1[k * HID + tid], acc);
        sH[tid] = fmaxf(acc + b1[tid], 0.0f);
    }
    __syncthreads();

    uint32_t lmax = 0;
    #pragma unroll
    for (int r = 0; r < 2; r++) {
        int v = tid + r * 256;
        float acc = 0.0f;
        #pragma unroll
        for (int j = 0; j < HID; j++)
            acc = fmaf(sH[j], W2[j * VOCAB + v], acc);
        float T = acc + b2[v];
        g_T[s * VOCAB + v] = T;
        // accept iff u2 < 1 - cr_expf(-(T*dt)); u2 = m*2^-23 exact
        float p = T * DT_F32;
        float e = (float)exp(-(double)p);       // correctly-rounded f32 exp
        float a = 1.0f - e;
        double d = ceil((double)a * 8388608.0);
        d = fmin(fmax(d, 0.0), 8388608.0);
        uint32_t th = (uint32_t)d;
        g_thr[s * VOCAB + v] = th;
        if (v != s) lmax = max(lmax, th);
    }
    #pragma unroll
    for (int off = 16; off; off >>= 1)
        lmax = max(lmax, __shfl_xor_sync(0xffffffffu, lmax, off));
    if ((tid & 31) == 0) sMax[tid >> 5] = lmax;
    __syncthreads();
    if (tid == 0) {
        uint32_t m = 0;
        #pragma unroll
        for (int w = 0; w < 8; w++) m = max(m, sMax[w]);
        g_pubm[s] = m;
    }
}

// ===================== fused step kernel ======================================
// Block handles 512 positions: reject-filter into a block-local smem queue,
// then warps run the exact categorical on the survivors.
__global__ void __launch_bounds__(256)
k_step(int t, const uint32_t* __restrict__ A, const uint32_t* __restrict__ B,
       uint32_t k1a, uint32_t k1b, uint32_t k2a, uint32_t k2b) {
    __shared__ int sq[POS_PER_BLOCK];
    __shared__ int sqn;
    int tid = threadIdx.x;
    if (tid == 0) sqn = 0;
    __syncthreads();

    int blockBase = blockIdx.x * POS_PER_BLOCK;
    const int* xin  = g_state[t & 1];
    int*       xout = g_state[(t + 1) & 1];
    int mode = get_xmode();
    const uint32_t* xp = (mode < 2) ? A : B;

    // ---- phase A: certain-reject filter (exact integer bound) ----
    #pragma unroll
    for (int r = 0; r < 2; r++) {
        int i = blockBase + tid + r * 256;
        int s;
        if (t == 0) {
            uint32_t w = xp[i];
            s = (mode & 1) ? (int)__uint_as_float(w) : (int)w;
            s = min(max(s, 0), VOCAB - 1);
        } else {
            s = xin[i];
        }
        xout[i] = s;
        uint32_t m = jax_bits32(k2a, k2b, (uint32_t)i) >> 9;
        if (m < g_pubm[s]) {
            int p = atomicAdd(&sqn, 1);       // <= 512 by construction
            sq[p] = (i << 9) | s;             // pack: pos(17b) | state(9b)
        }
    }
    __syncthreads();

    // ---- phase B: exact categorical, one warp per queued position ----
    int wid  = tid >> 5;
    int lane = tid & 31;
    int qn = sqn;
    for (int qi = wid; qi < qn; qi += 8) {
        int packed = sq[qi];
        int pos = packed >> 9;
        int s   = packed & 511;
        const float* __restrict__ row = g_T + (s << 9);
        uint32_t base = ((uint32_t)pos) << 9;

        // pass 1: fast gumbels (precise f32 logf, 1 ulp)
        float m1 = NEG_INF, m2 = NEG_INF;
        int   i1 = VOCAB;
        int   risky = 0;
        for (int i = 0; i < 16; i++) {
            int v = (i << 5) + lane;
            uint32_t bits = jax_bits32(k1a, k1b, base + (uint32_t)v);
            float u01 = bits_to_u01(bits);
            float u = fmaxf(TINY_F, u01 + TINY_F);
            float g = -logf(-logf(u));
            float cand = (v == s) ? NEG_INF : (row[v] + g);
            risky |= (u01 > 0.9999f && v != s);
            if (cand > m1) { m2 = m1; m1 = cand; i1 = v; }
            else if (cand > m2) { m2 = cand; }
        }
        #pragma unroll
        for (int off = 16; off; off >>= 1) {
            float o1 = __shfl_xor_sync(0xffffffffu, m1, off);
            int   oi = __shfl_xor_sync(0xffffffffu, i1, off);
            float o2 = __shfl_xor_sync(0xffffffffu, m2, off);
            if (o1 > m1 || (o1 == m1 && oi < i1)) {
                m2 = fmaxf(m1, o2); m1 = o1; i1 = oi;
            } else {
                m2 = fmaxf(m2, o1);
            }
        }
        int anyRisky = __ballot_sync(0xffffffffu, risky);
        int bidx = i1;

        // pass 2 (rare): exact CR recompute for near-max / risky draws
        if ((m1 - m2) < EPS2 || anyRisky) {
            float e1 = NEG_INF;
            int   ei = VOCAB;
            for (int i = 0; i < 16; i++) {
                int v = (i << 5) + lane;
                uint32_t bits = jax_bits32(k1a, k1b, base + (uint32_t)v);
                float u01 = bits_to_u01(bits);
                float u = fmaxf(TINY_F, u01 + TINY_F);
                float gf = -logf(-logf(u));
                float candf = row[v] + gf;
                if (v != s && (candf >= m1 - EPS2 || u01 > 0.9999f)) {
                    float r1 = (float)log((double)u);      // CR f32 log
                    float r2 = (float)log((double)(-r1));  // CR f32 log
                    float g  = -r2;
                    float cand = row[v] + g;               // exact reference chain
                    if (cand > e1) { e1 = cand; ei = v; }
                }
            }
            #pragma unroll
            for (int off = 16; off; off >>= 1) {
                float ov = __shfl_xor_sync(0xffffffffu, e1, off);
                int   oi = __shfl_xor_sync(0xffffffffu, ei, off);
                if (ov > e1 || (ov == e1 && oi < ei)) { e1 = ov; ei = oi; }
            }
            bidx = ei;
        }

        if (lane == 0) {
            uint32_t m = jax_bits32(k2a, k2b, (uint32_t)pos) >> 9;
            xout[pos] = (m < g_thr[(s << 9) | bidx]) ? bidx : s;
        }
    }
}

// ===================== launch =====================
extern "C" void kernel_launch(void* const* d_in, const int* in_sizes, int n_in,
                              void* d_out, int out_size) {
    (void)out_size;
    // -------- dual-convention size mapping (elements OR bytes) --------
    bool has_e_w1=false, has_e_b1=false, has_e_w2=false, has_e_b2=false;
    bool has_b_w1=false, has_b_b1=false, has_b_w2=false, has_b_b2=false;
    for (int i = 0; i < n_in; i++) {
        int sz = in_sizes[i];
        if (sz == 16384)  has_e_w1 = true;
        if (sz == 64)     has_e_b1 = true;
        if (sz == 32768)  has_e_w2 = true;
        if (sz == 512)    has_e_b2 = true;
        if (sz == 65536)  has_b_w1 = true;
        if (sz == 256)    has_b_b1 = true;
        if (sz == 131072) has_b_w2 = true;
        if (sz == 2048)   has_b_b2 = true;
    }
    bool elems_mode = has_e_w1 && has_e_b1 && has_e_w2 && has_e_b2;
    bool bytes_mode = !elems_mode && has_b_w1 && has_b_b1 && has_b_w2 && has_b_b2;

    const float *W1 = nullptr, *b1 = nullptr, *W2 = nullptr, *b2 = nullptr;
    const void  *cand[2] = { nullptr, nullptr };
    int ncand = 0;

    int s_w1 = elems_mode ? 16384  : 65536;
    int s_b1 = elems_mode ? 64     : 256;
    int s_w2 = elems_mode ? 32768  : 131072;
    int s_b2 = elems_mode ? 512    : 2048;
    int s_xe = elems_mode ? 131072 : 524288;

    if (elems_mode || bytes_mode) {
        for (int i = 0; i < n_in; i++) {
            int sz = in_sizes[i];
            if      (sz == s_w1) W1 = (const float*)d_in[i];
            else if (sz == s_b1) b1 = (const float*)d_in[i];
            else if (sz == s_w2) W2 = (const float*)d_in[i];
            else if (sz == s_b2) b2 = (const float*)d_in[i];
            else if (sz == s_xe) { if (ncand < 2) cand[ncand++] = d_in[i]; }
        }
    }

    bool ok = (elems_mode || bytes_mode) && W1 && b1 && W2 && b2 && ncand == 2;
    if (!ok) {
        k_fallback<<<(N_POS + 255) / 256, 256>>>((float*)d_out);
        return;
    }
    const uint32_t *bufA = (const uint32_t*)cand[0];
    const uint32_t *bufB = (const uint32_t*)cand[1];

    // -------- per-step keys (jax.random.key(42), partitionable fold-like) -----
    uint32_t k1a[N_STEPS], k1b[N_STEPS], k2a[N_STEPS], k2b[N_STEPS];
    for (int i = 0; i < N_STEPS; i++) {
        uint32_t sk0, sk1;
        h_tf2x32(0u, 42u, 0u, (uint32_t)i, sk0, sk1);
        h_tf2x32(sk0, sk1, 0u, 0u, k1a[i], k1b[i]);
        h_tf2x32(sk0, sk1, 0u, 1u, k2a[i], k2b[i]);
    }

    k_detect<<<64, 256>>>(bufA, bufB);
    k_table_fused<<<VOCAB, 256>>>(bufA, bufB, W1, b1, W2, b2);

    for (int t = 0; t < N_STEPS; t++)
        k_step<<<N_POS / POS_PER_BLOCK, 256>>>(t, bufA, bufB,
                                               k1a[t], k1b[t], k2a[t], k2b[t]);

    k_emit<<<(N_POS + 255) / 256, 256>>>((float*)d_out);
}